// round 2
// baseline (speedup 1.0000x reference)
#include <cuda_runtime.h>
#include <cuda_bf16.h>
#include <cstddef>

// Problem constants (fixed shapes from reference)
#define B_   64
#define T_   4096
#define F_   64
#define H_   256
#define LAM_ 0.5f
#define EPS_ 1e-8f
#define ALPHA_ 0.5f

// Chunked-scan parameters: lambda=0.5 => state memory ~ 0.5^WARM (negligible at 64)
#define CHUNK_  256
#define NCHUNK_ (T_ / CHUNK_)     // 16
#define WARM_   64

#define GRID_A  2048
#define TPB_A   256
#define GRID_B  (B_ * NCHUNK_)    // 1024
#define TPB_B   F_                // 64

// Scratch (device globals: no allocation allowed)
__device__ float g_G[B_ * T_];         // sum_h forget_gates[b,t,:]
__device__ float g_msePart[GRID_A];
__device__ float g_penPart[GRID_B];

// ---------------------------------------------------------------------------
// Kernel A: G[b,t] = sum_h fg[b,t,h]  (256 MB read, HBM-bound)  +  MSE partials
// ---------------------------------------------------------------------------
__global__ void __launch_bounds__(TPB_A) kA_rowsum_mse(
    const float* __restrict__ fg,
    const float* __restrict__ inp,
    const float* __restrict__ tgt)
{
    const int lane = threadIdx.x & 31;
    const int gwarp = (blockIdx.x * TPB_A + threadIdx.x) >> 5;
    const int nwarp = (GRID_A * TPB_A) >> 5;
    const float4* __restrict__ fg4 = (const float4*)fg;

    // Each warp reduces one row of 256 floats (2 float4 per lane, contiguous)
    for (int r = gwarp; r < B_ * T_; r += nwarp) {
        size_t base = (size_t)r * (H_ / 4);
        float4 a = fg4[base + lane];
        float4 b = fg4[base + 32 + lane];
        float s = (a.x + a.y) + (a.z + a.w) + (b.x + b.y) + (b.z + b.w);
        #pragma unroll
        for (int o = 16; o; o >>= 1) s += __shfl_xor_sync(0xffffffffu, s, o);
        if (lane == 0) g_G[r] = s;
    }

    // MSE partial over B*T elements
    float ms = 0.0f;
    const int gid = blockIdx.x * TPB_A + threadIdx.x;
    const int gsz = GRID_A * TPB_A;
    for (int i = gid; i < B_ * T_; i += gsz) {
        float d = inp[i] - tgt[i];
        ms = fmaf(d, d, ms);
    }
    __shared__ float sm[TPB_A / 32];
    #pragma unroll
    for (int o = 16; o; o >>= 1) ms += __shfl_xor_sync(0xffffffffu, ms, o);
    if (lane == 0) sm[threadIdx.x >> 5] = ms;
    __syncthreads();
    if (threadIdx.x < TPB_A / 32) {
        float v = sm[threadIdx.x];
        #pragma unroll
        for (int o = (TPB_A / 64); o; o >>= 1) v += __shfl_xor_sync(0xffu, v, o);
        if (threadIdx.x == 0) g_msePart[blockIdx.x] = v;
    }
}

// ---------------------------------------------------------------------------
// Kernel B: chunked EWA scan. Thread = (b, f, chunk). Accumulates
//   acc += (1 - |ac[b,t,f]|) * G[b,t]   over the chunk's t-range.
// ---------------------------------------------------------------------------
__device__ __forceinline__ void ewa_step(float& m, float& v, float& c,
                                         float xt, float xl)
{
    m = fmaf(0.5f, xt - m, m);          // m = 0.5 m + 0.5 xt
    float r = xt - m;
    v = fmaf(0.5f, fmaf(r, r, -v), v);  // v = 0.5 v + 0.5 r^2
    float q = xl - m;
    c = fmaf(0.5f, fmaf(r, q, -c), c);  // c = 0.5 c + 0.5 r q
}

__global__ void __launch_bounds__(TPB_B) kB_scan(const float* __restrict__ seq)
{
    const int b     = blockIdx.x / NCHUNK_;
    const int chunk = blockIdx.x % NCHUNK_;
    const int f     = threadIdx.x;

    const int t_begin = (chunk == 0) ? 1 : chunk * CHUNK_;
    const int t_end   = (chunk + 1) * CHUNK_;        // last chunk: 4096 (t<4096)

    const float* __restrict__ sp = seq + (size_t)b * T_ * F_ + f;
    const float* __restrict__ Gp = g_G + (size_t)b * T_;

    float m = 0.0f, v = EPS_, c = 0.0f;

    // Warm-up (exact init for chunk 0; truncated history otherwise)
    const int tw = (chunk == 0) ? 1 : (t_begin - WARM_);
    float xl = sp[(size_t)(tw - 1) * F_];
    for (int t = tw; t < t_begin; ++t) {
        float xt = sp[(size_t)t * F_];
        ewa_step(m, v, c, xt, xl);
        xl = xt;
    }

    // Main chunk: accumulate (1-|ac|)*G
    float acc = 0.0f;
    #pragma unroll 4
    for (int t = t_begin; t < t_end; ++t) {
        float xt = sp[(size_t)t * F_];
        ewa_step(m, v, c, xt, xl);
        xl = xt;
        float ac  = c * rsqrtf(fmaf(v, v, EPS_));
        float irr = 1.0f - fabsf(ac);
        acc = fmaf(irr, __ldg(Gp + t), acc);
    }

    // Block reduce (64 threads = 2 warps)
    #pragma unroll
    for (int o = 16; o; o >>= 1) acc += __shfl_xor_sync(0xffffffffu, acc, o);
    __shared__ float sm2[2];
    if ((threadIdx.x & 31) == 0) sm2[threadIdx.x >> 5] = acc;
    __syncthreads();
    if (threadIdx.x == 0) g_penPart[blockIdx.x] = sm2[0] + sm2[1];
}

// ---------------------------------------------------------------------------
// Kernel C: deterministic final reduce (double precision), writes scalar.
// ---------------------------------------------------------------------------
__global__ void __launch_bounds__(256) kC_finalize(float* __restrict__ out)
{
    double pen = 0.0, mse = 0.0;
    for (int i = threadIdx.x; i < GRID_B; i += 256) pen += (double)g_penPart[i];
    for (int i = threadIdx.x; i < GRID_A; i += 256) mse += (double)g_msePart[i];
    // t = 0 term: ac_full[0] = 0 -> irrelevance = 1 -> contributes F * G[b,0]
    if (threadIdx.x < B_) pen += (double)F_ * (double)g_G[(size_t)threadIdx.x * T_];

    __shared__ double sp[8], sq[8];
    const int lane = threadIdx.x & 31;
    #pragma unroll
    for (int o = 16; o; o >>= 1) {
        pen += __shfl_xor_sync(0xffffffffu, pen, o);
        mse += __shfl_xor_sync(0xffffffffu, mse, o);
    }
    if (lane == 0) { sp[threadIdx.x >> 5] = pen; sq[threadIdx.x >> 5] = mse; }
    __syncthreads();
    if (threadIdx.x == 0) {
        double P = 0.0, M = 0.0;
        #pragma unroll
        for (int i = 0; i < 8; ++i) { P += sp[i]; M += sq[i]; }
        double penalty = P / ((double)B_ * T_ * F_ * H_);
        double msev    = M / ((double)B_ * T_);
        out[0] = (float)(msev + (double)ALPHA_ * penalty);
    }
}

// ---------------------------------------------------------------------------
extern "C" void kernel_launch(void* const* d_in, const int* in_sizes, int n_in,
                              void* d_out, int out_size)
{
    const float* inp = (const float*)d_in[0];   // input   (B,T,1)
    const float* tgt = (const float*)d_in[1];   // target  (B,T,1)
    const float* seq = (const float*)d_in[2];   // sequence(B,T,F)
    const float* fg  = (const float*)d_in[3];   // forget_gates (B,T,H)
    float* out = (float*)d_out;

    kA_rowsum_mse<<<GRID_A, TPB_A>>>(fg, inp, tgt);
    kB_scan<<<GRID_B, TPB_B>>>(seq);
    kC_finalize<<<1, 256>>>(out);
}

// round 3
// speedup vs baseline: 1.2729x; 1.2729x over previous
#include <cuda_runtime.h>
#include <cuda_bf16.h>
#include <cstddef>

// Problem constants (fixed shapes from reference)
#define B_   64
#define T_   4096
#define F_   64
#define H_   256
#define LAM_ 0.5f
#define EPS_ 1e-8f
#define ALPHA_ 0.5f

// Chunked-scan parameters: lambda=0.5 => 0.5^40 ~ 1e-12, exact to fp32
#define CHUNK_  128
#define NCHUNK_ (T_ / CHUNK_)     // 32
#define WARM_   40

#define GRID_A  2048
#define TPB_A   256
#define GRID_B  (B_ * NCHUNK_)    // 2048
#define TPB_B   F_                // 64

// Scratch (device globals: no allocation allowed)
__device__ float g_G[B_ * T_];         // sum_h forget_gates[b,t,:]
__device__ float g_msePart[GRID_A];
__device__ float g_penPart[GRID_B];

// ---------------------------------------------------------------------------
// Kernel A: G[b,t] = sum_h fg[b,t,h]  (256 MB read, HBM-bound)  +  MSE partials
// Two rows per warp-iteration for doubled MLP / overlapped shuffle chains.
// ---------------------------------------------------------------------------
__global__ void __launch_bounds__(TPB_A) kA_rowsum_mse(
    const float* __restrict__ fg,
    const float* __restrict__ inp,
    const float* __restrict__ tgt)
{
    const int lane  = threadIdx.x & 31;
    const int gwarp = (blockIdx.x * TPB_A + threadIdx.x) >> 5;
    const int nwarp = (GRID_A * TPB_A) >> 5;      // 16384
    const float4* __restrict__ fg4 = (const float4*)fg;

    // 262144 rows / 16384 warps = 16 rows per warp -> 8 iterations of 2 rows
    for (int r = gwarp * 2; r < B_ * T_; r += nwarp * 2) {
        size_t b0 = (size_t)r * (H_ / 4);
        size_t b1 = (size_t)(r + 1) * (H_ / 4);
        float4 a0 = fg4[b0 + lane];
        float4 a1 = fg4[b0 + 32 + lane];
        float4 c0 = fg4[b1 + lane];
        float4 c1 = fg4[b1 + 32 + lane];
        float s0 = (a0.x + a0.y) + (a0.z + a0.w) + (a1.x + a1.y) + (a1.z + a1.w);
        float s1 = (c0.x + c0.y) + (c0.z + c0.w) + (c1.x + c1.y) + (c1.z + c1.w);
        #pragma unroll
        for (int o = 16; o; o >>= 1) {
            s0 += __shfl_xor_sync(0xffffffffu, s0, o);
            s1 += __shfl_xor_sync(0xffffffffu, s1, o);
        }
        if (lane == 0) { g_G[r] = s0; g_G[r + 1] = s1; }
    }

    // MSE partial over B*T elements
    float ms = 0.0f;
    const int gid = blockIdx.x * TPB_A + threadIdx.x;
    const int gsz = GRID_A * TPB_A;
    for (int i = gid; i < B_ * T_; i += gsz) {
        float d = inp[i] - tgt[i];
        ms = fmaf(d, d, ms);
    }
    __shared__ float sm[TPB_A / 32];
    #pragma unroll
    for (int o = 16; o; o >>= 1) ms += __shfl_xor_sync(0xffffffffu, ms, o);
    if (lane == 0) sm[threadIdx.x >> 5] = ms;
    __syncthreads();
    if (threadIdx.x < TPB_A / 32) {
        float v = sm[threadIdx.x];
        #pragma unroll
        for (int o = (TPB_A / 64); o; o >>= 1) v += __shfl_xor_sync(0xffu, v, o);
        if (threadIdx.x == 0) g_msePart[blockIdx.x] = v;
    }
}

// ---------------------------------------------------------------------------
// Kernel B: chunked EWA scan. Thread = (b, f, chunk). Accumulates
//   acc += (1 - |ac[b,t,f]|) * G[b,t]   over the chunk's t-range.
// ---------------------------------------------------------------------------
__device__ __forceinline__ void ewa_step(float& m, float& v, float& c,
                                         float xt, float xl)
{
    m = fmaf(0.5f, xt - m, m);          // m = 0.5 m + 0.5 xt
    float r = xt - m;
    v = fmaf(0.5f, fmaf(r, r, -v), v);  // v = 0.5 v + 0.5 r^2
    float q = xl - m;
    c = fmaf(0.5f, fmaf(r, q, -c), c);  // c = 0.5 c + 0.5 r q
}

__global__ void __launch_bounds__(TPB_B) kB_scan(const float* __restrict__ seq)
{
    const int b     = blockIdx.x / NCHUNK_;
    const int chunk = blockIdx.x % NCHUNK_;
    const int f     = threadIdx.x;

    const int t_begin = (chunk == 0) ? 1 : chunk * CHUNK_;
    const int t_end   = (chunk + 1) * CHUNK_;        // last chunk: 4096 (t<4096)

    const float* __restrict__ sp = seq + (size_t)b * T_ * F_ + f;
    const float* __restrict__ Gp = g_G + (size_t)b * T_;

    float m = 0.0f, v = EPS_, c = 0.0f;

    // Warm-up (exact init for chunk 0; truncated history otherwise)
    const int tw = (chunk == 0) ? 1 : (t_begin - WARM_);
    float xl = sp[(size_t)(tw - 1) * F_];
    #pragma unroll 4
    for (int t = tw; t < t_begin; ++t) {
        float xt = sp[(size_t)t * F_];
        ewa_step(m, v, c, xt, xl);
        xl = xt;
    }

    // Main chunk: accumulate (1-|ac|)*G
    float acc = 0.0f;
    #pragma unroll 4
    for (int t = t_begin; t < t_end; ++t) {
        float xt = sp[(size_t)t * F_];
        ewa_step(m, v, c, xt, xl);
        xl = xt;
        float ac  = c * rsqrtf(fmaf(v, v, EPS_));
        float irr = 1.0f - fabsf(ac);
        acc = fmaf(irr, __ldg(Gp + t), acc);
    }

    // Block reduce (64 threads = 2 warps)
    #pragma unroll
    for (int o = 16; o; o >>= 1) acc += __shfl_xor_sync(0xffffffffu, acc, o);
    __shared__ float sm2[2];
    if ((threadIdx.x & 31) == 0) sm2[threadIdx.x >> 5] = acc;
    __syncthreads();
    if (threadIdx.x == 0) g_penPart[blockIdx.x] = sm2[0] + sm2[1];
}

// ---------------------------------------------------------------------------
// Kernel C: deterministic final reduce (double precision), writes scalar.
// ---------------------------------------------------------------------------
__global__ void __launch_bounds__(256) kC_finalize(float* __restrict__ out)
{
    double pen = 0.0, mse = 0.0;
    for (int i = threadIdx.x; i < GRID_B; i += 256) pen += (double)g_penPart[i];
    for (int i = threadIdx.x; i < GRID_A; i += 256) mse += (double)g_msePart[i];
    // t = 0 term: ac_full[0] = 0 -> irrelevance = 1 -> contributes F * G[b,0]
    if (threadIdx.x < B_) pen += (double)F_ * (double)g_G[(size_t)threadIdx.x * T_];

    __shared__ double sp[8], sq[8];
    const int lane = threadIdx.x & 31;
    #pragma unroll
    for (int o = 16; o; o >>= 1) {
        pen += __shfl_xor_sync(0xffffffffu, pen, o);
        mse += __shfl_xor_sync(0xffffffffu, mse, o);
    }
    if (lane == 0) { sp[threadIdx.x >> 5] = pen; sq[threadIdx.x >> 5] = mse; }
    __syncthreads();
    if (threadIdx.x == 0) {
        double P = 0.0, M = 0.0;
        #pragma unroll
        for (int i = 0; i < 8; ++i) { P += sp[i]; M += sq[i]; }
        double penalty = P / ((double)B_ * T_ * F_ * H_);
        double msev    = M / ((double)B_ * T_);
        out[0] = (float)(msev + (double)ALPHA_ * penalty);
    }
}

// ---------------------------------------------------------------------------
extern "C" void kernel_launch(void* const* d_in, const int* in_sizes, int n_in,
                              void* d_out, int out_size)
{
    const float* inp = (const float*)d_in[0];   // input   (B,T,1)
    const float* tgt = (const float*)d_in[1];   // target  (B,T,1)
    const float* seq = (const float*)d_in[2];   // sequence(B,T,F)
    const float* fg  = (const float*)d_in[3];   // forget_gates (B,T,H)
    float* out = (float*)d_out;

    kA_rowsum_mse<<<GRID_A, TPB_A>>>(fg, inp, tgt);
    kB_scan<<<GRID_B, TPB_B>>>(seq);
    kC_finalize<<<1, 256>>>(out);
}

// round 4
// speedup vs baseline: 1.3497x; 1.0603x over previous
#include <cuda_runtime.h>
#include <cuda_bf16.h>
#include <cstddef>

// Problem constants (fixed shapes from reference)
#define B_   64
#define T_   4096
#define F_   64
#define H_   256
#define EPS_ 1e-8f
#define ALPHA_ 0.5f

// Fused layout: block = (b, chunk of 512 t), tiled by 32 t.
// lambda=0.5 => 0.5^40 ~ 1e-12: 40-step warm-up is exact to fp32.
#define CHUNK_  512
#define NCHUNK_ (T_ / CHUNK_)       // 8
#define WARM_   40
#define TILE_   32
#define NTILE_  (CHUNK_ / TILE_)    // 16

#define GRID_   (B_ * NCHUNK_)      // 512
#define TPB_    256

// Scratch (device globals: no allocation allowed)
__device__ float g_penPart[GRID_];
__device__ float g_msePart[GRID_];

__device__ __forceinline__ void ewa_step(float& m, float& v, float& c,
                                         float xt, float xl)
{
    m = fmaf(0.5f, xt - m, m);          // m = 0.5 m + 0.5 xt
    float r = xt - m;
    v = fmaf(0.5f, fmaf(r, r, -v), v);  // v = 0.5 v + 0.5 r^2
    float q = xl - m;
    c = fmaf(0.5f, fmaf(r, q, -c), c);  // c = 0.5 c + 0.5 r q
}

// ---------------------------------------------------------------------------
// Fused kernel: per block (b, chunk):
//   warps 2..7 : rowsum fg rows of tile k+1 -> smem G (double buffered)
//   warps 0..1 : EWA scan of tile k, acc += (1-|ac|) * G[t]
// Also computes MSE partials (grid-strided) in the prologue.
// ---------------------------------------------------------------------------
__global__ void __launch_bounds__(TPB_) kFused(
    const float* __restrict__ fg,
    const float* __restrict__ seq,
    const float* __restrict__ inp,
    const float* __restrict__ tgt)
{
    __shared__ float Gs[2][TILE_];
    __shared__ float redM[TPB_ / 32];
    __shared__ float redP[2];

    const int tid  = threadIdx.x;
    const int wid  = tid >> 5;
    const int lane = tid & 31;
    const int b     = blockIdx.x >> 3;          // / NCHUNK_
    const int chunk = blockIdx.x & (NCHUNK_ - 1);
    const int t0    = chunk * CHUNK_;

    const float4* __restrict__ fg4 = (const float4*)fg;

    // ---- MSE partial (262144 elems over 131072 threads) ----
    float ms = 0.0f;
    for (int i = blockIdx.x * TPB_ + tid; i < B_ * T_; i += GRID_ * TPB_) {
        float d = inp[i] - tgt[i];
        ms = fmaf(d, d, ms);
    }

    // ---- Pre-phase: warps 2-7 rowsum tile 0; warps 0-1 warm up the scan ----
    float m = 0.0f, v = EPS_, c = 0.0f, xl = 0.0f, acc = 0.0f;
    const float* __restrict__ sp = seq + (size_t)b * T_ * F_ + tid; // tid<64 only

    if (wid >= 2) {
        const size_t rowbase = (size_t)(b * T_ + t0) * (H_ / 4);
        for (int rl = wid - 2; rl < TILE_; rl += 6) {
            size_t base = rowbase + (size_t)rl * (H_ / 4);
            float4 a0 = fg4[base + lane];
            float4 a1 = fg4[base + 32 + lane];
            float s = (a0.x + a0.y) + (a0.z + a0.w) + (a1.x + a1.y) + (a1.z + a1.w);
            #pragma unroll
            for (int o = 16; o; o >>= 1) s += __shfl_xor_sync(0xffffffffu, s, o);
            if (lane == 0) Gs[0][rl] = s;
        }
    } else {
        if (chunk == 0) {
            xl = sp[0];                          // x[t=0]; scan starts at t=1
        } else {
            const int tw = t0 - WARM_;
            xl = sp[(size_t)(tw - 1) * F_];
            #pragma unroll 4
            for (int t = tw; t < t0; ++t) {
                float xt = sp[(size_t)t * F_];
                ewa_step(m, v, c, xt, xl);
                xl = xt;
            }
        }
    }
    __syncthreads();

    // ---- Tile-pipelined main loop ----
    for (int tl = 0; tl < NTILE_; ++tl) {
        if (wid >= 2) {
            // rowsum tile tl+1 into the other buffer
            if (tl + 1 < NTILE_) {
                const int bb = (tl + 1) & 1;
                const size_t rowbase =
                    (size_t)(b * T_ + t0 + (tl + 1) * TILE_) * (H_ / 4);
                for (int rl = wid - 2; rl < TILE_; rl += 6) {
                    size_t base = rowbase + (size_t)rl * (H_ / 4);
                    float4 a0 = fg4[base + lane];
                    float4 a1 = fg4[base + 32 + lane];
                    float s = (a0.x + a0.y) + (a0.z + a0.w) +
                              (a1.x + a1.y) + (a1.z + a1.w);
                    #pragma unroll
                    for (int o = 16; o; o >>= 1)
                        s += __shfl_xor_sync(0xffffffffu, s, o);
                    if (lane == 0) Gs[bb][rl] = s;
                }
            }
        } else {
            // scan tile tl
            const int bb = tl & 1;
            const int tb = t0 + tl * TILE_;
            #pragma unroll 8
            for (int j = 0; j < TILE_; ++j) {
                const int t = tb + j;
                const float g = Gs[bb][j];
                if (t == 0) {
                    // ac_full[0] = 0 -> irrelevance = 1 for every f
                    acc += g;
                } else {
                    float xt = sp[(size_t)t * F_];
                    ewa_step(m, v, c, xt, xl);
                    xl = xt;
                    float ac = c * rsqrtf(fmaf(v, v, EPS_));
                    acc = fmaf(1.0f - fabsf(ac), g, acc);
                }
            }
        }
        __syncthreads();
    }

    // ---- Block reductions: ms (all 8 warps), acc (warps 0-1) ----
    #pragma unroll
    for (int o = 16; o; o >>= 1) {
        ms  += __shfl_xor_sync(0xffffffffu, ms, o);
        acc += __shfl_xor_sync(0xffffffffu, acc, o);
    }
    if (lane == 0) {
        redM[wid] = ms;
        if (wid < 2) redP[wid] = acc;
    }
    __syncthreads();
    if (tid == 0) {
        float M = 0.0f;
        #pragma unroll
        for (int i = 0; i < TPB_ / 32; ++i) M += redM[i];
        g_msePart[blockIdx.x] = M;
        g_penPart[blockIdx.x] = redP[0] + redP[1];
    }
}

// ---------------------------------------------------------------------------
// Finalize: deterministic double-precision reduce of 512+512 partials.
// ---------------------------------------------------------------------------
__global__ void __launch_bounds__(256) kC_finalize(float* __restrict__ out)
{
    double pen = 0.0, mse = 0.0;
    for (int i = threadIdx.x; i < GRID_; i += 256) {
        pen += (double)g_penPart[i];
        mse += (double)g_msePart[i];
    }
    __shared__ double sp[8], sq[8];
    const int lane = threadIdx.x & 31;
    #pragma unroll
    for (int o = 16; o; o >>= 1) {
        pen += __shfl_xor_sync(0xffffffffu, pen, o);
        mse += __shfl_xor_sync(0xffffffffu, mse, o);
    }
    if (lane == 0) { sp[threadIdx.x >> 5] = pen; sq[threadIdx.x >> 5] = mse; }
    __syncthreads();
    if (threadIdx.x == 0) {
        double P = 0.0, M = 0.0;
        #pragma unroll
        for (int i = 0; i < 8; ++i) { P += sp[i]; M += sq[i]; }
        double penalty = P / ((double)B_ * T_ * F_ * H_);
        double msev    = M / ((double)B_ * T_);
        out[0] = (float)(msev + (double)ALPHA_ * penalty);
    }
}

// ---------------------------------------------------------------------------
extern "C" void kernel_launch(void* const* d_in, const int* in_sizes, int n_in,
                              void* d_out, int out_size)
{
    const float* inp = (const float*)d_in[0];   // input    (B,T,1)
    const float* tgt = (const float*)d_in[1];   // target   (B,T,1)
    const float* seq = (const float*)d_in[2];   // sequence (B,T,F)
    const float* fg  = (const float*)d_in[3];   // forget_gates (B,T,H)
    float* out = (float*)d_out;

    kFused<<<GRID_, TPB_>>>(fg, seq, inp, tgt);
    kC_finalize<<<1, 256>>>(out);
}

// round 6
// speedup vs baseline: 1.3878x; 1.0282x over previous
#include <cuda_runtime.h>
#include <cuda_bf16.h>
#include <cstddef>

// Problem constants (fixed shapes from reference)
#define B_   64
#define T_   4096
#define F_   64
#define H_   256
#define EPS_ 1e-8f
#define ALPHA_ 0.5f

// Chunking: lambda=0.5 => 0.5^40 ~ 1e-12, warm-up of 40 is exact to fp32.
#define CHUNK_  256
#define NCHUNK_ (T_ / CHUNK_)       // 16
#define WARM_   40

#define GRID_   (B_ * NCHUNK_)      // 1024
#define TPB_    256

// Scratch (device globals: no allocation allowed)
__device__ float g_penPart[GRID_];
__device__ float g_msePart[GRID_];
__device__ int   g_ticket;          // zero-initialized; reset by last block

__device__ __forceinline__ void ewa_step(float& m, float& v, float& c,
                                         float xt, float xl)
{
    m = fmaf(0.5f, xt - m, m);          // m = 0.5 m + 0.5 xt
    float r = xt - m;
    v = fmaf(0.5f, fmaf(r, r, -v), v);  // v = 0.5 v + 0.5 r^2
    float q = xl - m;
    c = fmaf(0.5f, fmaf(r, q, -c), c);  // c = 0.5 c + 0.5 r q
}

// ---------------------------------------------------------------------------
// One fused kernel. Block = (b, chunk of 256 t).
//   Phase 1: ALL 8 warps rowsum the chunk's 256 fg rows -> smem G (1 barrier)
//   Phase 2: warps 0-1 (64 threads = F) warm up + scan, acc += (1-|ac|)*G[t]
//   Epilogue: block partials -> global; last block reduces in double & writes.
// ---------------------------------------------------------------------------
__global__ void __launch_bounds__(TPB_) kFused(
    const float* __restrict__ fg,
    const float* __restrict__ seq,
    const float* __restrict__ inp,
    const float* __restrict__ tgt,
    float* __restrict__ out)
{
    __shared__ float  Gs[CHUNK_];
    __shared__ float  redM[TPB_ / 32];
    __shared__ float  redP[2];
    __shared__ int    s_ticket;
    __shared__ double dP[TPB_ / 32], dM[TPB_ / 32];

    const int tid  = threadIdx.x;
    const int wid  = tid >> 5;
    const int lane = tid & 31;
    const int b     = blockIdx.x >> 4;            // / NCHUNK_
    const int chunk = blockIdx.x & (NCHUNK_ - 1);
    const int t0    = chunk * CHUNK_;

    const float4* __restrict__ fg4 = (const float4*)fg;

    // ---- MSE: exactly one element per thread (B*T == GRID_*TPB_) ----
    float ms;
    {
        const int i = blockIdx.x * TPB_ + tid;
        float d = inp[i] - tgt[i];
        ms = d * d;
    }

    // ---- Phase 1: all warps rowsum 256 rows, 2 rows per warp-iteration ----
    {
        const size_t rowbase = (size_t)(b * T_ + t0) * (H_ / 4);
        #pragma unroll 2
        for (int r = wid * 2; r < CHUNK_; r += 16) {
            size_t b0 = rowbase + (size_t)r * (H_ / 4);
            size_t b1 = b0 + (H_ / 4);
            float4 a0 = fg4[b0 + lane];
            float4 a1 = fg4[b0 + 32 + lane];
            float4 c0 = fg4[b1 + lane];
            float4 c1 = fg4[b1 + 32 + lane];
            float s0 = (a0.x + a0.y) + (a0.z + a0.w) + (a1.x + a1.y) + (a1.z + a1.w);
            float s1 = (c0.x + c0.y) + (c0.z + c0.w) + (c1.x + c1.y) + (c1.z + c1.w);
            #pragma unroll
            for (int o = 16; o; o >>= 1) {
                s0 += __shfl_xor_sync(0xffffffffu, s0, o);
                s1 += __shfl_xor_sync(0xffffffffu, s1, o);
            }
            if (lane == 0) { Gs[r] = s0; Gs[r + 1] = s1; }
        }
    }
    __syncthreads();

    // ---- Phase 2: warps 0-1 scan (thread = feature f) ----
    float acc = 0.0f;
    if (wid < 2) {
        const float* __restrict__ sp = seq + (size_t)b * T_ * F_ + tid;
        float m = 0.0f, v = EPS_, c = 0.0f, xl;

        int t_begin;
        if (chunk == 0) {
            xl = sp[0];
            acc = Gs[0];                 // t=0: irr = 1 for every f
            t_begin = 1;
        } else {
            const int tw = t0 - WARM_;
            xl = sp[(size_t)(tw - 1) * F_];
            #pragma unroll 4
            for (int t = tw; t < t0; ++t) {
                float xt = sp[(size_t)t * F_];
                ewa_step(m, v, c, xt, xl);
                xl = xt;
            }
            t_begin = t0;
        }

        #pragma unroll 8
        for (int t = t_begin; t < t0 + CHUNK_; ++t) {
            float xt = sp[(size_t)t * F_];
            ewa_step(m, v, c, xt, xl);
            xl = xt;
            float ac = c * rsqrtf(fmaf(v, v, EPS_));
            acc = fmaf(1.0f - fabsf(ac), Gs[t - t0], acc);
        }
    }

    // ---- Block reductions ----
    #pragma unroll
    for (int o = 16; o; o >>= 1) {
        ms  += __shfl_xor_sync(0xffffffffu, ms, o);
        acc += __shfl_xor_sync(0xffffffffu, acc, o);
    }
    if (lane == 0) {
        redM[wid] = ms;
        if (wid < 2) redP[wid] = acc;
    }
    __syncthreads();
    if (tid == 0) {
        float M = 0.0f;
        #pragma unroll
        for (int i = 0; i < TPB_ / 32; ++i) M += redM[i];
        g_msePart[blockIdx.x] = M;
        g_penPart[blockIdx.x] = redP[0] + redP[1];
        __threadfence();
        s_ticket = atomicAdd(&g_ticket, 1);
    }
    __syncthreads();

    // ---- Last block: deterministic double-precision finalize ----
    if (s_ticket == GRID_ - 1) {
        double pen = 0.0, mse = 0.0;
        for (int i = tid; i < GRID_; i += TPB_) {
            pen += (double)g_penPart[i];
            mse += (double)g_msePart[i];
        }
        #pragma unroll
        for (int o = 16; o; o >>= 1) {
            pen += __shfl_xor_sync(0xffffffffu, pen, o);
            mse += __shfl_xor_sync(0xffffffffu, mse, o);
        }
        if (lane == 0) { dP[wid] = pen; dM[wid] = mse; }
        __syncthreads();
        if (tid == 0) {
            double P = 0.0, M = 0.0;
            #pragma unroll
            for (int i = 0; i < TPB_ / 32; ++i) { P += dP[i]; M += dM[i]; }
            double penalty = P / ((double)B_ * T_ * F_ * H_);
            double msev    = M / ((double)B_ * T_);
            out[0] = (float)(msev + (double)ALPHA_ * penalty);
            g_ticket = 0;                 // reset for next graph replay
        }
    }
}

// ---------------------------------------------------------------------------
extern "C" void kernel_launch(void* const* d_in, const int* in_sizes, int n_in,
                              void* d_out, int out_size)
{
    const float* inp = (const float*)d_in[0];   // input    (B,T,1)
    const float* tgt = (const float*)d_in[1];   // target   (B,T,1)
    const float* seq = (const float*)d_in[2];   // sequence (B,T,F)
    const float* fg  = (const float*)d_in[3];   // forget_gates (B,T,H)
    float* out = (float*)d_out;

    kFused<<<GRID_, TPB_>>>(fg, seq, inp, tgt, out);
}

// round 7
// speedup vs baseline: 1.6516x; 1.1901x over previous
#include <cuda_runtime.h>
#include <cuda_bf16.h>
#include <cstddef>

// Problem constants (fixed shapes from reference)
#define B_   64
#define T_   4096
#define F_   64
#define H_   256
#define EPS_ 1e-8f
#define ALPHA_ 0.5f

// Chunking: block owns 256 t; scan split into 4 sub-chunks of 64 t (one per
// warp-pair). lambda=0.5 => 0.5^40 ~ 1e-12: 40-step warm-up exact to fp32.
#define CHUNK_  256
#define NCHUNK_ (T_ / CHUNK_)       // 16
#define SUB_    64
#define NSUB_   (CHUNK_ / SUB_)     // 4
#define WARM_   40

#define GRID_   (B_ * NCHUNK_)      // 1024
#define TPB_    256

// Scratch (device globals: no allocation allowed)
__device__ float g_penPart[GRID_];
__device__ float g_msePart[GRID_];
__device__ int   g_ticket;          // zero-initialized; reset by last block

__device__ __forceinline__ void ewa_step(float& m, float& v, float& c,
                                         float xt, float xl)
{
    m = fmaf(0.5f, xt - m, m);          // m = 0.5 m + 0.5 xt
    float r = xt - m;
    v = fmaf(0.5f, fmaf(r, r, -v), v);  // v = 0.5 v + 0.5 r^2
    float q = xl - m;
    c = fmaf(0.5f, fmaf(r, q, -c), c);  // c = 0.5 c + 0.5 r q
}

// ---------------------------------------------------------------------------
// One fused kernel. Block = (b, chunk of 256 t).
//   Phase 1: ALL 8 warps rowsum the chunk's 256 fg rows -> smem G (1 barrier)
//   Phase 2: ALL 8 warps scan: warp-pair g handles t in [t0+64g, t0+64g+64)
//            (own 40-step warm-up), acc += (1-|ac|)*G[t]
//   Epilogue: block partials -> global; last block reduces in double & writes.
// ---------------------------------------------------------------------------
__global__ void __launch_bounds__(TPB_) kFused(
    const float* __restrict__ fg,
    const float* __restrict__ seq,
    const float* __restrict__ inp,
    const float* __restrict__ tgt,
    float* __restrict__ out)
{
    __shared__ float  Gs[CHUNK_];
    __shared__ float  redA[TPB_ / 32];
    __shared__ float  redM[TPB_ / 32];
    __shared__ int    s_ticket;
    __shared__ double dP[TPB_ / 32], dM[TPB_ / 32];

    const int tid  = threadIdx.x;
    const int wid  = tid >> 5;
    const int lane = tid & 31;
    const int b     = blockIdx.x >> 4;            // / NCHUNK_
    const int chunk = blockIdx.x & (NCHUNK_ - 1);
    const int t0    = chunk * CHUNK_;

    const float4* __restrict__ fg4 = (const float4*)fg;

    // ---- MSE: exactly one element per thread (B*T == GRID_*TPB_) ----
    float ms;
    {
        const int i = blockIdx.x * TPB_ + tid;
        float d = inp[i] - tgt[i];
        ms = d * d;
    }

    // ---- Phase 1: all 8 warps rowsum 256 rows, 2 rows per warp-iteration ----
    {
        const size_t rowbase = (size_t)(b * T_ + t0) * (H_ / 4);
        #pragma unroll 2
        for (int r = wid * 2; r < CHUNK_; r += 16) {
            size_t b0 = rowbase + (size_t)r * (H_ / 4);
            size_t b1 = b0 + (H_ / 4);
            float4 a0 = fg4[b0 + lane];
            float4 a1 = fg4[b0 + 32 + lane];
            float4 c0 = fg4[b1 + lane];
            float4 c1 = fg4[b1 + 32 + lane];
            float s0 = (a0.x + a0.y) + (a0.z + a0.w) + (a1.x + a1.y) + (a1.z + a1.w);
            float s1 = (c0.x + c0.y) + (c0.z + c0.w) + (c1.x + c1.y) + (c1.z + c1.w);
            #pragma unroll
            for (int o = 16; o; o >>= 1) {
                s0 += __shfl_xor_sync(0xffffffffu, s0, o);
                s1 += __shfl_xor_sync(0xffffffffu, s1, o);
            }
            if (lane == 0) { Gs[r] = s0; Gs[r + 1] = s1; }
        }
    }
    __syncthreads();

    // ---- Phase 2: all 8 warps scan; warp-pair g = tid>>6 owns 64 t ----
    float acc = 0.0f;
    {
        const int f  = tid & (F_ - 1);
        const int g  = tid >> 6;                  // sub-chunk 0..3
        const int ts = t0 + g * SUB_;             // sub-chunk start
        const float* __restrict__ sp = seq + (size_t)b * T_ * F_ + f;

        float m = 0.0f, v = EPS_, c = 0.0f, xl;

        int t_begin;
        if (ts == 0) {
            xl  = sp[0];
            acc = Gs[0];                          // t=0: irr = 1 for every f
            t_begin = 1;
        } else {
            const int tw = ts - WARM_;            // >= 24 always
            xl = sp[(size_t)(tw - 1) * F_];
            #pragma unroll 4
            for (int t = tw; t < ts; ++t) {
                float xt = sp[(size_t)t * F_];
                ewa_step(m, v, c, xt, xl);
                xl = xt;
            }
            t_begin = ts;
        }

        #pragma unroll 8
        for (int t = t_begin; t < ts + SUB_; ++t) {
            float xt = sp[(size_t)t * F_];
            ewa_step(m, v, c, xt, xl);
            xl = xt;
            float ac = c * rsqrtf(fmaf(v, v, EPS_));
            acc = fmaf(1.0f - fabsf(ac), Gs[t - t0], acc);
        }
    }

    // ---- Block reductions (all 8 warps carry both acc and ms) ----
    #pragma unroll
    for (int o = 16; o; o >>= 1) {
        ms  += __shfl_xor_sync(0xffffffffu, ms, o);
        acc += __shfl_xor_sync(0xffffffffu, acc, o);
    }
    if (lane == 0) { redM[wid] = ms; redA[wid] = acc; }
    __syncthreads();
    if (tid == 0) {
        float M = 0.0f, A = 0.0f;
        #pragma unroll
        for (int i = 0; i < TPB_ / 32; ++i) { M += redM[i]; A += redA[i]; }
        g_msePart[blockIdx.x] = M;
        g_penPart[blockIdx.x] = A;
        __threadfence();
        s_ticket = atomicAdd(&g_ticket, 1);
    }
    __syncthreads();

    // ---- Last block: deterministic double-precision finalize ----
    if (s_ticket == GRID_ - 1) {
        double pen = 0.0, mse = 0.0;
        for (int i = tid; i < GRID_; i += TPB_) {
            pen += (double)g_penPart[i];
            mse += (double)g_msePart[i];
        }
        #pragma unroll
        for (int o = 16; o; o >>= 1) {
            pen += __shfl_xor_sync(0xffffffffu, pen, o);
            mse += __shfl_xor_sync(0xffffffffu, mse, o);
        }
        if (lane == 0) { dP[wid] = pen; dM[wid] = mse; }
        __syncthreads();
        if (tid == 0) {
            double P = 0.0, M = 0.0;
            #pragma unroll
            for (int i = 0; i < TPB_ / 32; ++i) { P += dP[i]; M += dM[i]; }
            double penalty = P / ((double)B_ * T_ * F_ * H_);
            double msev    = M / ((double)B_ * T_);
            out[0] = (float)(msev + (double)ALPHA_ * penalty);
            g_ticket = 0;                 // reset for next graph replay
        }
    }
}

// ---------------------------------------------------------------------------
extern "C" void kernel_launch(void* const* d_in, const int* in_sizes, int n_in,
                              void* d_out, int out_size)
{
    const float* inp = (const float*)d_in[0];   // input    (B,T,1)
    const float* tgt = (const float*)d_in[1];   // target   (B,T,1)
    const float* seq = (const float*)d_in[2];   // sequence (B,T,F)
    const float* fg  = (const float*)d_in[3];   // forget_gates (B,T,H)
    float* out = (float*)d_out;

    kFused<<<GRID_, TPB_>>>(fg, seq, inp, tgt, out);
}